// round 14
// baseline (speedup 1.0000x reference)
#include <cuda_runtime.h>
#include <stdint.h>

#define N_NODES 200000
#define N_ETYPES 4
#define N_EDGES 500000
#define DIM 128
#define M_BINS (N_ETYPES * N_NODES)       // 800000 (etype, dst) bins
#define TOTAL_EDGES (N_ETYPES * N_EDGES)  // 2000000
#define SCAN_B 1024
#define NB ((M_BINS + SCAN_B - 1) / SCAN_B)   // 782 scan blocks

// ---------------- scratch (static __device__ — no allocations) ----------------
__device__ float g_Wx[(size_t)N_ETYPES * N_NODES * DIM];   // 409.6 MB
__device__ int g_cnt[M_BINS];        // per-(etype,dst) in-degree
__device__ int g_off[M_BINS];        // CSR row offsets (exclusive scan of cnt)
__device__ int g_cur[M_BINS];        // bucket cursors (copy of offsets)
__device__ int g_csr[TOTAL_EDGES];   // src node ids grouped by (etype,dst)
__device__ int g_bsum[SCAN_B];       // scan block sums (NB <= 1024)

// ---------------- prep kernels -------------------------------------------------
__global__ void zero_cnt_kernel() {
    int i = blockIdx.x * blockDim.x + threadIdx.x;
    if (i < M_BINS) g_cnt[i] = 0;
}

__global__ void count_kernel(const int* __restrict__ dst) {
    int i = blockIdx.x * blockDim.x + threadIdx.x;
    if (i < TOTAL_EDGES) {
        int t = i / N_EDGES;
        atomicAdd(&g_cnt[t * N_NODES + dst[i]], 1);
    }
}

__global__ __launch_bounds__(SCAN_B)
void scan_sums_kernel() {
    __shared__ int s[SCAN_B];
    int t = threadIdx.x;
    int i = blockIdx.x * SCAN_B + t;
    s[t] = (i < M_BINS) ? g_cnt[i] : 0;
    __syncthreads();
#pragma unroll
    for (int o = SCAN_B / 2; o > 0; o >>= 1) {
        if (t < o) s[t] += s[t + o];
        __syncthreads();
    }
    if (t == 0) g_bsum[blockIdx.x] = s[0];
}

__global__ __launch_bounds__(SCAN_B)
void scan_tops_kernel() {
    __shared__ int s[SCAN_B];
    int t = threadIdx.x;
    int own = (t < NB) ? g_bsum[t] : 0;
    s[t] = own;
    __syncthreads();
#pragma unroll
    for (int o = 1; o < SCAN_B; o <<= 1) {
        int v = (t >= o) ? s[t - o] : 0;
        __syncthreads();
        s[t] += v;
        __syncthreads();
    }
    if (t < NB) g_bsum[t] = s[t] - own;   // exclusive
}

__global__ __launch_bounds__(SCAN_B)
void scan_final_kernel() {
    __shared__ int s[SCAN_B];
    int t = threadIdx.x;
    int i = blockIdx.x * SCAN_B + t;
    int own = (i < M_BINS) ? g_cnt[i] : 0;
    s[t] = own;
    __syncthreads();
#pragma unroll
    for (int o = 1; o < SCAN_B; o <<= 1) {
        int v = (t >= o) ? s[t - o] : 0;
        __syncthreads();
        s[t] += v;
        __syncthreads();
    }
    if (i < M_BINS) {
        int ex = s[t] - own + g_bsum[blockIdx.x];
        g_off[i] = ex;
        g_cur[i] = ex;
    }
}

__global__ void bucket_kernel(const int* __restrict__ src,
                              const int* __restrict__ dst) {
    int i = blockIdx.x * blockDim.x + threadIdx.x;
    if (i < TOTAL_EDGES) {
        int t = i / N_EDGES;
        int pos = atomicAdd(&g_cur[t * N_NODES + dst[i]], 1);
        g_csr[pos] = src[i];
    }
}

// ---------------- kernel: fused 5-way TF32 GEMM, B from L1/L2 -----------------
// One block owns a 128-row tile of x (tf32 in smem, loaded ONCE), loops bt=0..4
// over the 5 weight matrices. B fragments come straight from global via __ldg
// (W is 320KB total, L1/L2-resident after wave 1) — no B smem, so smem drops to
// 67.6KB and 2 blocks fit per SM (occupancy 12.7% -> 25%).
// 256 threads = 8 warps in 2(m) x 4(n); warp tile 64x32 = 4 m16 x 4 n8.

#define BM 128
#define AS 132    // A smem stride: frag bank = (4g+tg)%32 -> conflict-free
#define SMEM_BYTES (BM * AS * 4)

__device__ __forceinline__ uint32_t f2tf32(float f) {
    uint32_t u;
    asm("cvt.rna.tf32.f32 %0, %1;" : "=r"(u) : "f"(f));
    return u;
}

__device__ __forceinline__ void mma_tf32(float c[4], const uint32_t a[4],
                                         const uint32_t bb[2]) {
    asm volatile(
        "mma.sync.aligned.m16n8k8.row.col.f32.tf32.tf32.f32 "
        "{%0,%1,%2,%3}, {%4,%5,%6,%7}, {%8,%9}, {%0,%1,%2,%3};"
        : "+f"(c[0]), "+f"(c[1]), "+f"(c[2]), "+f"(c[3])
        : "r"(a[0]), "r"(a[1]), "r"(a[2]), "r"(a[3]), "r"(bb[0]), "r"(bb[1]));
}

__global__ __launch_bounds__(256, 2)
void gemm_fused_kernel(const float* __restrict__ x,
                       const float* __restrict__ W,
                       const float* __restrict__ b,
                       const float* __restrict__ W_self,
                       const float* __restrict__ b_self,
                       float* __restrict__ out) {
    extern __shared__ float smem[];
    float* As = smem;                    // [BM][AS], tf32 bit patterns

    const int row0 = blockIdx.x * BM;
    const int tid  = threadIdx.x;
    const int warp = tid >> 5;
    const int lane = tid & 31;
    const int wm   = warp >> 2;        // 0..1
    const int wn   = warp & 3;         // 0..3
    const int g    = lane >> 2;        // 0..7
    const int tg   = lane & 3;         // 0..3

    const float* Bm[5] = {W, W + DIM * DIM, W + 2 * DIM * DIM,
                          W + 3 * DIM * DIM, W_self};
    const float* bi[5] = {b, b + DIM, b + 2 * DIM, b + 3 * DIM, b_self};

    // stage A tile once: 128x128 fp32 -> tf32 in smem
#pragma unroll
    for (int it = 0; it < 16; it++) {
        int idx = tid + it * 256;
        int r   = idx >> 5;
        int c4  = (idx & 31) * 4;
        int gr  = row0 + r;
        float4 v = make_float4(0.f, 0.f, 0.f, 0.f);
        if (gr < N_NODES)
            v = *reinterpret_cast<const float4*>(x + (size_t)gr * DIM + c4);
        uint4 t;
        t.x = f2tf32(v.x); t.y = f2tf32(v.y);
        t.z = f2tf32(v.z); t.w = f2tf32(v.w);
        *reinterpret_cast<uint4*>(&As[r * AS + c4]) = t;
    }
    __syncthreads();

    float acc[4][4][4];

#pragma unroll 1
    for (int bt = 0; bt < 5; bt++) {
        const float* Bp = Bm[bt];

#pragma unroll
        for (int i = 0; i < 4; i++)
#pragma unroll
            for (int j = 0; j < 4; j++)
#pragma unroll
                for (int k = 0; k < 4; k++) acc[i][j][k] = 0.0f;

#pragma unroll
        for (int ks = 0; ks < DIM; ks += 8) {
            uint32_t bfr[4][2];
#pragma unroll
            for (int nt = 0; nt < 4; nt++) {
                int c = wn * 32 + nt * 8 + g;
                bfr[nt][0] = f2tf32(__ldg(&Bp[(ks + tg) * DIM + c]));
                bfr[nt][1] = f2tf32(__ldg(&Bp[(ks + tg + 4) * DIM + c]));
            }
            uint32_t afr[4][4];
#pragma unroll
            for (int mt = 0; mt < 4; mt++) {
                int r = wm * 64 + mt * 16 + g;
                afr[mt][0] = __float_as_uint(As[r * AS + ks + tg]);
                afr[mt][1] = __float_as_uint(As[(r + 8) * AS + ks + tg]);
                afr[mt][2] = __float_as_uint(As[r * AS + ks + tg + 4]);
                afr[mt][3] = __float_as_uint(As[(r + 8) * AS + ks + tg + 4]);
            }
#pragma unroll
            for (int mt = 0; mt < 4; mt++)
#pragma unroll
                for (int nt = 0; nt < 4; nt++)
                    mma_tf32(acc[mt][nt], afr[mt], bfr[nt]);
        }

        const float* bias = bi[bt];
        float* C = (bt < 4) ? (g_Wx + ((size_t)bt * N_NODES + row0) * DIM)
                            : (out + (size_t)row0 * DIM);
#pragma unroll
        for (int nt = 0; nt < 4; nt++) {
            int c = wn * 32 + nt * 8 + tg * 2;
            float b0 = __ldg(&bias[c]);
            float b1 = __ldg(&bias[c + 1]);
#pragma unroll
            for (int mt = 0; mt < 4; mt++) {
                int r_lo = wm * 64 + mt * 16 + g;
                if (row0 + r_lo < N_NODES) {
                    float2 v0 = make_float2(acc[mt][nt][0] + b0,
                                            acc[mt][nt][1] + b1);
                    *reinterpret_cast<float2*>(C + (size_t)r_lo * DIM + c) = v0;
                }
                if (row0 + r_lo + 8 < N_NODES) {
                    float2 v1 = make_float2(acc[mt][nt][2] + b0,
                                            acc[mt][nt][3] + b1);
                    *reinterpret_cast<float2*>(C + (size_t)(r_lo + 8) * DIM + c) = v1;
                }
            }
        }
    }
}

// ---------------- kernel: CSR gather-sum, 4-etype interleaved (MLP up) --------
// One warp per dst node. All 4 etype CSR segments walked in lockstep with
// predicated loads -> 4-8 independent loads in flight per thread.
__global__ __launch_bounds__(256)
void gather_sum_kernel(float* __restrict__ out) {
    int w    = (blockIdx.x * blockDim.x + threadIdx.x) >> 5;
    int lane = threadIdx.x & 31;
    if (w >= N_NODES) return;
    const int d = w;
    const int c4 = lane << 2;

    int n[N_ETYPES], base[N_ETYPES];
#pragma unroll
    for (int t = 0; t < N_ETYPES; t++) {
        int bin = t * N_NODES + d;
        n[t]    = __ldg(&g_cnt[bin]);
        base[t] = __ldg(&g_off[bin]);
    }

    float4 a[N_ETYPES];
#pragma unroll
    for (int t = 0; t < N_ETYPES; t++)
        a[t] = make_float4(0.f, 0.f, 0.f, 0.f);

    int nmax = max(max(n[0], n[1]), max(n[2], n[3]));
    for (int k = 0; k < nmax; k++) {
        int s[N_ETYPES];
#pragma unroll
        for (int t = 0; t < N_ETYPES; t++)
            if (k < n[t]) s[t] = __ldg(&g_csr[base[t] + k]);
        float4 v[N_ETYPES];
#pragma unroll
        for (int t = 0; t < N_ETYPES; t++)
            if (k < n[t])
                v[t] = *reinterpret_cast<const float4*>(
                    g_Wx + ((size_t)t * N_NODES + s[t]) * DIM + c4);
#pragma unroll
        for (int t = 0; t < N_ETYPES; t++)
            if (k < n[t]) {
                a[t].x += v[t].x; a[t].y += v[t].y;
                a[t].z += v[t].z; a[t].w += v[t].w;
            }
    }

    float4 o = *reinterpret_cast<const float4*>(out + (size_t)d * DIM + c4);
#pragma unroll
    for (int t = 0; t < N_ETYPES; t++) {
        if (n[t] > 0) {
            float sc = 1.0f / (float)n[t];
            o.x += a[t].x * sc; o.y += a[t].y * sc;
            o.z += a[t].z * sc; o.w += a[t].w * sc;
        }
    }
    *reinterpret_cast<float4*>(out + (size_t)d * DIM + c4) = o;
}

// ---------------- launcher ----------------
extern "C" void kernel_launch(void* const* d_in, const int* in_sizes, int n_in,
                              void* d_out, int out_size) {
    const float* x      = (const float*)d_in[0];   // [200000,128]
    const float* W      = (const float*)d_in[1];   // [4,128,128]
    const float* b      = (const float*)d_in[2];   // [4,128]
    const float* W_self = (const float*)d_in[3];   // [128,128]
    const float* b_self = (const float*)d_in[4];   // [128]
    const int*   src    = (const int*)d_in[5];     // [4,500000]
    const int*   dst    = (const int*)d_in[6];     // [4,500000]
    float* out = (float*)d_out;                    // [200000,128]

    (void)in_sizes; (void)n_in; (void)out_size;

    // --- CSR build: count -> scan -> bucket ---
    zero_cnt_kernel<<<(M_BINS + 255) / 256, 256>>>();
    count_kernel<<<(TOTAL_EDGES + 255) / 256, 256>>>(dst);
    scan_sums_kernel<<<NB, SCAN_B>>>();
    scan_tops_kernel<<<1, SCAN_B>>>();
    scan_final_kernel<<<NB, SCAN_B>>>();
    bucket_kernel<<<(TOTAL_EDGES + 255) / 256, 256>>>(src, dst);

    // --- fused 5-way tf32 GEMM: Wx[0..3] scratch + self message into out ---
    cudaFuncSetAttribute(gemm_fused_kernel,
                         cudaFuncAttributeMaxDynamicSharedMemorySize,
                         SMEM_BYTES);
    int grid = (N_NODES + BM - 1) / BM;
    gemm_fused_kernel<<<grid, 256, SMEM_BYTES>>>(x, W, b, W_self, b_self, out);

    // --- CSR gather-sum: out[d] += sum_t mean_{src in N_t(d)} Wx[t][src] ---
    {
        long long threads = (long long)N_NODES * 32;
        int blocks = (int)((threads + 255) / 256);
        gather_sum_kernel<<<blocks, 256>>>(out);
    }
}

// round 15
// speedup vs baseline: 1.1007x; 1.1007x over previous
#include <cuda_runtime.h>
#include <stdint.h>

#define N_NODES 200000
#define N_ETYPES 4
#define N_EDGES 500000
#define DIM 128
#define M_BINS (N_ETYPES * N_NODES)       // 800000 (etype, dst) bins
#define TOTAL_EDGES (N_ETYPES * N_EDGES)  // 2000000
#define SCAN_B 1024
#define NB ((M_BINS + SCAN_B - 1) / SCAN_B)   // 782 scan blocks

// ---------------- scratch (static __device__ — no allocations) ----------------
__device__ float g_Wx[(size_t)N_ETYPES * N_NODES * DIM];   // 409.6 MB
__device__ int g_cnt[M_BINS];        // per-(etype,dst) in-degree
__device__ int g_off[M_BINS];        // CSR row offsets (exclusive scan of cnt)
__device__ int g_cur[M_BINS];        // bucket cursors (copy of offsets)
__device__ int g_csr[TOTAL_EDGES];   // src node ids grouped by (etype,dst)
__device__ int g_bsum[SCAN_B];       // scan block sums (NB <= 1024)

// ---------------- prep kernels -------------------------------------------------
__global__ void zero_cnt_kernel() {
    int i = blockIdx.x * blockDim.x + threadIdx.x;
    if (i < M_BINS) g_cnt[i] = 0;
}

__global__ void count_kernel(const int* __restrict__ dst) {
    int i = blockIdx.x * blockDim.x + threadIdx.x;
    if (i < TOTAL_EDGES) {
        int t = i / N_EDGES;
        atomicAdd(&g_cnt[t * N_NODES + dst[i]], 1);
    }
}

__global__ __launch_bounds__(SCAN_B)
void scan_sums_kernel() {
    __shared__ int s[SCAN_B];
    int t = threadIdx.x;
    int i = blockIdx.x * SCAN_B + t;
    s[t] = (i < M_BINS) ? g_cnt[i] : 0;
    __syncthreads();
#pragma unroll
    for (int o = SCAN_B / 2; o > 0; o >>= 1) {
        if (t < o) s[t] += s[t + o];
        __syncthreads();
    }
    if (t == 0) g_bsum[blockIdx.x] = s[0];
}

__global__ __launch_bounds__(SCAN_B)
void scan_tops_kernel() {
    __shared__ int s[SCAN_B];
    int t = threadIdx.x;
    int own = (t < NB) ? g_bsum[t] : 0;
    s[t] = own;
    __syncthreads();
#pragma unroll
    for (int o = 1; o < SCAN_B; o <<= 1) {
        int v = (t >= o) ? s[t - o] : 0;
        __syncthreads();
        s[t] += v;
        __syncthreads();
    }
    if (t < NB) g_bsum[t] = s[t] - own;   // exclusive
}

__global__ __launch_bounds__(SCAN_B)
void scan_final_kernel() {
    __shared__ int s[SCAN_B];
    int t = threadIdx.x;
    int i = blockIdx.x * SCAN_B + t;
    int own = (i < M_BINS) ? g_cnt[i] : 0;
    s[t] = own;
    __syncthreads();
#pragma unroll
    for (int o = 1; o < SCAN_B; o <<= 1) {
        int v = (t >= o) ? s[t - o] : 0;
        __syncthreads();
        s[t] += v;
        __syncthreads();
    }
    if (i < M_BINS) {
        int ex = s[t] - own + g_bsum[blockIdx.x];
        g_off[i] = ex;
        g_cur[i] = ex;
    }
}

__global__ void bucket_kernel(const int* __restrict__ src,
                              const int* __restrict__ dst) {
    int i = blockIdx.x * blockDim.x + threadIdx.x;
    if (i < TOTAL_EDGES) {
        int t = i / N_EDGES;
        int pos = atomicAdd(&g_cur[t * N_NODES + dst[i]], 1);
        g_csr[pos] = src[i];
    }
}

// ---------------- kernel: fused 5-way TF32 GEMM, 512 threads ------------------
// One block owns a 128-row tile of x (tf32 in smem, loaded ONCE), loops bt=0..4
// over the 5 weight matrices with cp.async double-buffered B tiles (proven R12
// structure). 512 threads = 16 warps in 4(m) x 4(n); warp tile 32x32 =
// 2 m16 x 4 n8. Same smem (207KB, 1 block/SM) but 16 warps/SM instead of 8.

#define BM 128
#define AS 132    // A smem stride: frag bank = (4g+tg)%32 -> conflict-free
#define BSD 136   // B smem stride: frag bank = (8tg+g)%32 -> conflict-free
#define SMEM_FLOATS (BM * AS + 2 * DIM * BSD)
#define SMEM_BYTES (SMEM_FLOATS * 4)

__device__ __forceinline__ uint32_t f2tf32(float f) {
    uint32_t u;
    asm("cvt.rna.tf32.f32 %0, %1;" : "=r"(u) : "f"(f));
    return u;
}

__device__ __forceinline__ void mma_tf32(float c[4], const uint32_t a[4],
                                         const uint32_t bb[2]) {
    asm volatile(
        "mma.sync.aligned.m16n8k8.row.col.f32.tf32.tf32.f32 "
        "{%0,%1,%2,%3}, {%4,%5,%6,%7}, {%8,%9}, {%0,%1,%2,%3};"
        : "+f"(c[0]), "+f"(c[1]), "+f"(c[2]), "+f"(c[3])
        : "r"(a[0]), "r"(a[1]), "r"(a[2]), "r"(a[3]), "r"(bb[0]), "r"(bb[1]));
}

__device__ __forceinline__ void cp_async_tile512(float* sdst,
                                                 const float* __restrict__ gsrc,
                                                 int tid) {
#pragma unroll
    for (int it = 0; it < 8; it++) {
        int idx = tid + it * 512;
        int r   = idx >> 5;            // 0..127
        int c4  = (idx & 31) * 4;      // 0..124
        uint32_t s = (uint32_t)__cvta_generic_to_shared(sdst + r * BSD + c4);
        asm volatile("cp.async.ca.shared.global [%0], [%1], 16;"
                     :: "r"(s), "l"(gsrc + (size_t)r * DIM + c4));
    }
}

__global__ __launch_bounds__(512, 1)
void gemm_fused_kernel(const float* __restrict__ x,
                       const float* __restrict__ W,
                       const float* __restrict__ b,
                       const float* __restrict__ W_self,
                       const float* __restrict__ b_self,
                       float* __restrict__ out) {
    extern __shared__ float smem[];
    float* As    = smem;                 // [BM][AS], tf32 bit patterns
    float* BsAll = smem + BM * AS;       // [2][DIM][BSD], raw fp32 via cp.async

    const int row0 = blockIdx.x * BM;
    const int tid  = threadIdx.x;
    const int warp = tid >> 5;         // 0..15
    const int lane = tid & 31;
    const int wm   = warp >> 2;        // 0..3  (32 rows each)
    const int wn   = warp & 3;         // 0..3  (32 cols each)
    const int g    = lane >> 2;        // 0..7
    const int tg   = lane & 3;         // 0..3

    const float* Bm[5] = {W, W + DIM * DIM, W + 2 * DIM * DIM,
                          W + 3 * DIM * DIM, W_self};
    const float* bi[5] = {b, b + DIM, b + 2 * DIM, b + 3 * DIM, b_self};

    // prefetch B[0] (overlaps the A staging below)
    cp_async_tile512(BsAll, Bm[0], tid);
    asm volatile("cp.async.commit_group;");

    // stage A tile once: 128x128 fp32 -> tf32 in smem
#pragma unroll
    for (int it = 0; it < 8; it++) {
        int idx = tid + it * 512;
        int r   = idx >> 5;
        int c4  = (idx & 31) * 4;
        int gr  = row0 + r;
        float4 v = make_float4(0.f, 0.f, 0.f, 0.f);
        if (gr < N_NODES)
            v = *reinterpret_cast<const float4*>(x + (size_t)gr * DIM + c4);
        uint4 t;
        t.x = f2tf32(v.x); t.y = f2tf32(v.y);
        t.z = f2tf32(v.z); t.w = f2tf32(v.w);
        *reinterpret_cast<uint4*>(&As[r * AS + c4]) = t;
    }

    float acc[2][4][4];

    for (int bt = 0; bt < 5; bt++) {
        float* Bbuf = BsAll + (bt & 1) * (DIM * BSD);

        asm volatile("cp.async.wait_group 0;" ::: "memory");
        __syncthreads();   // B[bt] visible; all warps done with other buffer

        if (bt < 4) {
            cp_async_tile512(BsAll + ((bt + 1) & 1) * (DIM * BSD),
                             Bm[bt + 1], tid);
            asm volatile("cp.async.commit_group;");
        }

#pragma unroll
        for (int i = 0; i < 2; i++)
#pragma unroll
            for (int j = 0; j < 4; j++)
#pragma unroll
                for (int k = 0; k < 4; k++) acc[i][j][k] = 0.0f;

#pragma unroll
        for (int ks = 0; ks < DIM; ks += 8) {
            uint32_t afr[2][4];
#pragma unroll
            for (int mt = 0; mt < 2; mt++) {
                int r = wm * 32 + mt * 16 + g;
                afr[mt][0] = __float_as_uint(As[r * AS + ks + tg]);
                afr[mt][1] = __float_as_uint(As[(r + 8) * AS + ks + tg]);
                afr[mt][2] = __float_as_uint(As[r * AS + ks + tg + 4]);
                afr[mt][3] = __float_as_uint(As[(r + 8) * AS + ks + tg + 4]);
            }
            uint32_t bfr[4][2];
#pragma unroll
            for (int nt = 0; nt < 4; nt++) {
                int c = wn * 32 + nt * 8 + g;
                bfr[nt][0] = f2tf32(Bbuf[(ks + tg) * BSD + c]);
                bfr[nt][1] = f2tf32(Bbuf[(ks + tg + 4) * BSD + c]);
            }
#pragma unroll
            for (int mt = 0; mt < 2; mt++)
#pragma unroll
                for (int nt = 0; nt < 4; nt++)
                    mma_tf32(acc[mt][nt], afr[mt], bfr[nt]);
        }

        // epilogue for this bt
        const float* bias = bi[bt];
        float* C = (bt < 4) ? (g_Wx + ((size_t)bt * N_NODES + row0) * DIM)
                            : (out + (size_t)row0 * DIM);
#pragma unroll
        for (int nt = 0; nt < 4; nt++) {
            int c = wn * 32 + nt * 8 + tg * 2;
            float b0 = __ldg(&bias[c]);
            float b1 = __ldg(&bias[c + 1]);
#pragma unroll
            for (int mt = 0; mt < 2; mt++) {
                int r_lo = wm * 32 + mt * 16 + g;
                if (row0 + r_lo < N_NODES) {
                    float2 v0 = make_float2(acc[mt][nt][0] + b0,
                                            acc[mt][nt][1] + b1);
                    *reinterpret_cast<float2*>(C + (size_t)r_lo * DIM + c) = v0;
                }
                if (row0 + r_lo + 8 < N_NODES) {
                    float2 v1 = make_float2(acc[mt][nt][2] + b0,
                                            acc[mt][nt][3] + b1);
                    *reinterpret_cast<float2*>(C + (size_t)(r_lo + 8) * DIM + c) = v1;
                }
            }
        }
    }
}

// ---------------- kernel: CSR gather-sum (R12-proven, sequential etypes) ------
// One warp per dst node. For each etype, walk the contiguous CSR segment,
// gather Wx[t][src] rows (unroll-2 for MLP), scale by 1/cnt, accumulate in
// registers together with the self message already in out[d]; single plain
// float4 store per lane. Zero atomics.
__global__ __launch_bounds__(256)
void gather_sum_kernel(float* __restrict__ out) {
    int w    = (blockIdx.x * blockDim.x + threadIdx.x) >> 5;
    int lane = threadIdx.x & 31;
    if (w >= N_NODES) return;
    const int d = w;
    const int c4 = lane << 2;   // this lane's 4-float slice of the row

    float4 o = *reinterpret_cast<const float4*>(out + (size_t)d * DIM + c4);

#pragma unroll
    for (int t = 0; t < N_ETYPES; t++) {
        const int bin = t * N_NODES + d;
        const int n    = __ldg(&g_cnt[bin]);
        if (n == 0) continue;
        const int base = __ldg(&g_off[bin]);
        const float* WxT = g_Wx + (size_t)t * N_NODES * DIM;

        float4 a0 = make_float4(0.f, 0.f, 0.f, 0.f);
        float4 a1 = make_float4(0.f, 0.f, 0.f, 0.f);
        int j = 0;
        for (; j + 2 <= n; j += 2) {
            int s0 = __ldg(&g_csr[base + j]);
            int s1 = __ldg(&g_csr[base + j + 1]);
            float4 v0 = *reinterpret_cast<const float4*>(
                WxT + (size_t)s0 * DIM + c4);
            float4 v1 = *reinterpret_cast<const float4*>(
                WxT + (size_t)s1 * DIM + c4);
            a0.x += v0.x; a0.y += v0.y; a0.z += v0.z; a0.w += v0.w;
            a1.x += v1.x; a1.y += v1.y; a1.z += v1.z; a1.w += v1.w;
        }
        if (j < n) {
            int s0 = __ldg(&g_csr[base + j]);
            float4 v0 = *reinterpret_cast<const float4*>(
                WxT + (size_t)s0 * DIM + c4);
            a0.x += v0.x; a0.y += v0.y; a0.z += v0.z; a0.w += v0.w;
        }
        float sc = 1.0f / (float)n;
        o.x += (a0.x + a1.x) * sc;
        o.y += (a0.y + a1.y) * sc;
        o.z += (a0.z + a1.z) * sc;
        o.w += (a0.w + a1.w) * sc;
    }

    *reinterpret_cast<float4*>(out + (size_t)d * DIM + c4) = o;
}

// ---------------- launcher ----------------
extern "C" void kernel_launch(void* const* d_in, const int* in_sizes, int n_in,
                              void* d_out, int out_size) {
    const float* x      = (const float*)d_in[0];   // [200000,128]
    const float* W      = (const float*)d_in[1];   // [4,128,128]
    const float* b      = (const float*)d_in[2];   // [4,128]
    const float* W_self = (const float*)d_in[3];   // [128,128]
    const float* b_self = (const float*)d_in[4];   // [128]
    const int*   src    = (const int*)d_in[5];     // [4,500000]
    const int*   dst    = (const int*)d_in[6];     // [4,500000]
    float* out = (float*)d_out;                    // [200000,128]

    (void)in_sizes; (void)n_in; (void)out_size;

    // --- CSR build: count -> scan -> bucket ---
    zero_cnt_kernel<<<(M_BINS + 255) / 256, 256>>>();
    count_kernel<<<(TOTAL_EDGES + 255) / 256, 256>>>(dst);
    scan_sums_kernel<<<NB, SCAN_B>>>();
    scan_tops_kernel<<<1, SCAN_B>>>();
    scan_final_kernel<<<NB, SCAN_B>>>();
    bucket_kernel<<<(TOTAL_EDGES + 255) / 256, 256>>>(src, dst);

    // --- fused 5-way tf32 GEMM: Wx[0..3] scratch + self message into out ---
    cudaFuncSetAttribute(gemm_fused_kernel,
                         cudaFuncAttributeMaxDynamicSharedMemorySize,
                         SMEM_BYTES);
    int grid = (N_NODES + BM - 1) / BM;
    gemm_fused_kernel<<<grid, 512, SMEM_BYTES>>>(x, W, b, W_self, b_self, out);

    // --- CSR gather-sum: out[d] += sum_t mean_{src in N_t(d)} Wx[t][src] ---
    {
        long long threads = (long long)N_NODES * 32;
        int blocks = (int)((threads + 255) / 256);
        gather_sum_kernel<<<blocks, 256>>>(out);
    }
}

// round 16
// speedup vs baseline: 1.1709x; 1.0637x over previous
#include <cuda_runtime.h>
#include <cuda_fp16.h>
#include <stdint.h>

#define N_NODES 200000
#define N_ETYPES 4
#define N_EDGES 500000
#define DIM 128
#define M_BINS (N_ETYPES * N_NODES)       // 800000 (etype, dst) bins
#define TOTAL_EDGES (N_ETYPES * N_EDGES)  // 2000000
#define SCAN_B 1024
#define NB ((M_BINS + SCAN_B - 1) / SCAN_B)   // 782 scan blocks

// ---------------- scratch (static __device__ — no allocations) ----------------
__device__ __half g_Wx[(size_t)N_ETYPES * N_NODES * DIM];  // 204.8 MB (fp16)
__device__ int g_cnt[M_BINS];        // per-(etype,dst) in-degree
__device__ int g_off[M_BINS];        // CSR row offsets (exclusive scan of cnt)
__device__ int g_cur[M_BINS];        // bucket cursors (copy of offsets)
__device__ int g_csr[TOTAL_EDGES];   // src node ids grouped by (etype,dst)
__device__ int g_bsum[SCAN_B];       // scan block sums (NB <= 1024)

// ---------------- prep kernels -------------------------------------------------
__global__ void zero_cnt_kernel() {
    int i = blockIdx.x * blockDim.x + threadIdx.x;
    if (i < M_BINS) g_cnt[i] = 0;
}

__global__ void count_kernel(const int* __restrict__ dst) {
    int i = blockIdx.x * blockDim.x + threadIdx.x;
    if (i < TOTAL_EDGES) {
        int t = i / N_EDGES;
        atomicAdd(&g_cnt[t * N_NODES + dst[i]], 1);
    }
}

__global__ __launch_bounds__(SCAN_B)
void scan_sums_kernel() {
    __shared__ int s[SCAN_B];
    int t = threadIdx.x;
    int i = blockIdx.x * SCAN_B + t;
    s[t] = (i < M_BINS) ? g_cnt[i] : 0;
    __syncthreads();
#pragma unroll
    for (int o = SCAN_B / 2; o > 0; o >>= 1) {
        if (t < o) s[t] += s[t + o];
        __syncthreads();
    }
    if (t == 0) g_bsum[blockIdx.x] = s[0];
}

__global__ __launch_bounds__(SCAN_B)
void scan_tops_kernel() {
    __shared__ int s[SCAN_B];
    int t = threadIdx.x;
    int own = (t < NB) ? g_bsum[t] : 0;
    s[t] = own;
    __syncthreads();
#pragma unroll
    for (int o = 1; o < SCAN_B; o <<= 1) {
        int v = (t >= o) ? s[t - o] : 0;
        __syncthreads();
        s[t] += v;
        __syncthreads();
    }
    if (t < NB) g_bsum[t] = s[t] - own;   // exclusive
}

__global__ __launch_bounds__(SCAN_B)
void scan_final_kernel() {
    __shared__ int s[SCAN_B];
    int t = threadIdx.x;
    int i = blockIdx.x * SCAN_B + t;
    int own = (i < M_BINS) ? g_cnt[i] : 0;
    s[t] = own;
    __syncthreads();
#pragma unroll
    for (int o = 1; o < SCAN_B; o <<= 1) {
        int v = (t >= o) ? s[t - o] : 0;
        __syncthreads();
        s[t] += v;
        __syncthreads();
    }
    if (i < M_BINS) {
        int ex = s[t] - own + g_bsum[blockIdx.x];
        g_off[i] = ex;
        g_cur[i] = ex;
    }
}

__global__ void bucket_kernel(const int* __restrict__ src,
                              const int* __restrict__ dst) {
    int i = blockIdx.x * blockDim.x + threadIdx.x;
    if (i < TOTAL_EDGES) {
        int t = i / N_EDGES;
        int pos = atomicAdd(&g_cur[t * N_NODES + dst[i]], 1);
        g_csr[pos] = src[i];
    }
}

// ---------------- kernel: fused 5-way TF32 GEMM (R12-proven structure) --------
// One block owns a 128-row tile of x (tf32 in smem, loaded ONCE), loops bt=0..4
// over the 5 weight matrices with cp.async double-buffered B tiles.
// bt<4 -> g_Wx[bt] scratch in FP16 (halves write traffic), bt==4 -> fp32 out.
// 256 threads = 8 warps in 2(m) x 4(n); warp tile 64x32 = 4 m16 x 4 n8.

#define BM 128
#define AS 132    // A smem stride: frag bank = (4g+tg)%32 -> conflict-free
#define BSD 136   // B smem stride: frag bank = (8tg+g)%32 -> conflict-free
#define SMEM_FLOATS (BM * AS + 2 * DIM * BSD)
#define SMEM_BYTES (SMEM_FLOATS * 4)

__device__ __forceinline__ uint32_t f2tf32(float f) {
    uint32_t u;
    asm("cvt.rna.tf32.f32 %0, %1;" : "=r"(u) : "f"(f));
    return u;
}

__device__ __forceinline__ void mma_tf32(float c[4], const uint32_t a[4],
                                         const uint32_t bb[2]) {
    asm volatile(
        "mma.sync.aligned.m16n8k8.row.col.f32.tf32.tf32.f32 "
        "{%0,%1,%2,%3}, {%4,%5,%6,%7}, {%8,%9}, {%0,%1,%2,%3};"
        : "+f"(c[0]), "+f"(c[1]), "+f"(c[2]), "+f"(c[3])
        : "r"(a[0]), "r"(a[1]), "r"(a[2]), "r"(a[3]), "r"(bb[0]), "r"(bb[1]));
}

__device__ __forceinline__ void cp_async_tile(float* sdst,
                                              const float* __restrict__ gsrc,
                                              int tid) {
#pragma unroll
    for (int it = 0; it < 16; it++) {
        int idx = tid + it * 256;
        int r   = idx >> 5;            // 0..127
        int c4  = (idx & 31) * 4;      // 0..124
        uint32_t s = (uint32_t)__cvta_generic_to_shared(sdst + r * BSD + c4);
        asm volatile("cp.async.ca.shared.global [%0], [%1], 16;"
                     :: "r"(s), "l"(gsrc + (size_t)r * DIM + c4));
    }
}

__global__ __launch_bounds__(256)
void gemm_fused_kernel(const float* __restrict__ x,
                       const float* __restrict__ W,
                       const float* __restrict__ b,
                       const float* __restrict__ W_self,
                       const float* __restrict__ b_self,
                       float* __restrict__ out) {
    extern __shared__ float smem[];
    float* As    = smem;                 // [BM][AS], tf32 bit patterns
    float* BsAll = smem + BM * AS;       // [2][DIM][BSD], raw fp32 via cp.async

    const int row0 = blockIdx.x * BM;
    const int tid  = threadIdx.x;
    const int warp = tid >> 5;
    const int lane = tid & 31;
    const int wm   = warp >> 2;        // 0..1
    const int wn   = warp & 3;         // 0..3
    const int g    = lane >> 2;        // 0..7
    const int tg   = lane & 3;         // 0..3

    const float* Bm[5] = {W, W + DIM * DIM, W + 2 * DIM * DIM,
                          W + 3 * DIM * DIM, W_self};
    const float* bi[5] = {b, b + DIM, b + 2 * DIM, b + 3 * DIM, b_self};

    cp_async_tile(BsAll, Bm[0], tid);
    asm volatile("cp.async.commit_group;");

    // stage A tile once: 128x128 fp32 -> tf32 in smem
#pragma unroll
    for (int it = 0; it < 16; it++) {
        int idx = tid + it * 256;
        int r   = idx >> 5;
        int c4  = (idx & 31) * 4;
        int gr  = row0 + r;
        float4 v = make_float4(0.f, 0.f, 0.f, 0.f);
        if (gr < N_NODES)
            v = *reinterpret_cast<const float4*>(x + (size_t)gr * DIM + c4);
        uint4 t;
        t.x = f2tf32(v.x); t.y = f2tf32(v.y);
        t.z = f2tf32(v.z); t.w = f2tf32(v.w);
        *reinterpret_cast<uint4*>(&As[r * AS + c4]) = t;
    }

    float acc[4][4][4];

    for (int bt = 0; bt < 5; bt++) {
        float* Bbuf = BsAll + (bt & 1) * (DIM * BSD);

        asm volatile("cp.async.wait_group 0;" ::: "memory");
        __syncthreads();

        if (bt < 4) {
            cp_async_tile(BsAll + ((bt + 1) & 1) * (DIM * BSD), Bm[bt + 1], tid);
            asm volatile("cp.async.commit_group;");
        }

#pragma unroll
        for (int i = 0; i < 4; i++)
#pragma unroll
            for (int j = 0; j < 4; j++)
#pragma unroll
                for (int k = 0; k < 4; k++) acc[i][j][k] = 0.0f;

#pragma unroll
        for (int ks = 0; ks < DIM; ks += 8) {
            uint32_t afr[4][4];
#pragma unroll
            for (int mt = 0; mt < 4; mt++) {
                int r = wm * 64 + mt * 16 + g;
                afr[mt][0] = __float_as_uint(As[r * AS + ks + tg]);
                afr[mt][1] = __float_as_uint(As[(r + 8) * AS + ks + tg]);
                afr[mt][2] = __float_as_uint(As[r * AS + ks + tg + 4]);
                afr[mt][3] = __float_as_uint(As[(r + 8) * AS + ks + tg + 4]);
            }
            uint32_t bfr[4][2];
#pragma unroll
            for (int nt = 0; nt < 4; nt++) {
                int c = wn * 32 + nt * 8 + g;
                bfr[nt][0] = f2tf32(Bbuf[(ks + tg) * BSD + c]);
                bfr[nt][1] = f2tf32(Bbuf[(ks + tg + 4) * BSD + c]);
            }
#pragma unroll
            for (int mt = 0; mt < 4; mt++)
#pragma unroll
                for (int nt = 0; nt < 4; nt++)
                    mma_tf32(acc[mt][nt], afr[mt], bfr[nt]);
        }

        const float* bias = bi[bt];
        if (bt < 4) {
            // fp16 scratch store
            __half* C = g_Wx + ((size_t)bt * N_NODES + row0) * DIM;
#pragma unroll
            for (int nt = 0; nt < 4; nt++) {
                int c = wn * 32 + nt * 8 + tg * 2;
                float b0 = __ldg(&bias[c]);
                float b1 = __ldg(&bias[c + 1]);
#pragma unroll
                for (int mt = 0; mt < 4; mt++) {
                    int r_lo = wm * 64 + mt * 16 + g;
                    if (row0 + r_lo < N_NODES) {
                        __half2 h = __floats2half2_rn(acc[mt][nt][0] + b0,
                                                      acc[mt][nt][1] + b1);
                        *reinterpret_cast<__half2*>(
                            C + (size_t)r_lo * DIM + c) = h;
                    }
                    if (row0 + r_lo + 8 < N_NODES) {
                        __half2 h = __floats2half2_rn(acc[mt][nt][2] + b0,
                                                      acc[mt][nt][3] + b1);
                        *reinterpret_cast<__half2*>(
                            C + (size_t)(r_lo + 8) * DIM + c) = h;
                    }
                }
            }
        } else {
            // fp32 self message into out
            float* C = out + (size_t)row0 * DIM;
#pragma unroll
            for (int nt = 0; nt < 4; nt++) {
                int c = wn * 32 + nt * 8 + tg * 2;
                float b0 = __ldg(&bias[c]);
                float b1 = __ldg(&bias[c + 1]);
#pragma unroll
                for (int mt = 0; mt < 4; mt++) {
                    int r_lo = wm * 64 + mt * 16 + g;
                    if (row0 + r_lo < N_NODES) {
                        float2 v0 = make_float2(acc[mt][nt][0] + b0,
                                                acc[mt][nt][1] + b1);
                        *reinterpret_cast<float2*>(
                            C + (size_t)r_lo * DIM + c) = v0;
                    }
                    if (row0 + r_lo + 8 < N_NODES) {
                        float2 v1 = make_float2(acc[mt][nt][2] + b0,
                                                acc[mt][nt][3] + b1);
                        *reinterpret_cast<float2*>(
                            C + (size_t)(r_lo + 8) * DIM + c) = v1;
                    }
                }
            }
        }
    }
}

// ---------------- kernel: CSR gather-sum over fp16 Wx -------------------------
// One warp per dst node. For each etype, walk the contiguous CSR segment,
// gather fp16 Wx rows (8B per lane, unroll-2 for MLP), accumulate in fp32,
// scale by 1/cnt, add to the self message already in out[d]; single plain
// float4 store per lane. Zero atomics.
__global__ __launch_bounds__(256)
void gather_sum_kernel(float* __restrict__ out) {
    int w    = (blockIdx.x * blockDim.x + threadIdx.x) >> 5;
    int lane = threadIdx.x & 31;
    if (w >= N_NODES) return;
    const int d = w;
    const int c4 = lane << 2;   // this lane's 4-element slice of the row

    float4 o = *reinterpret_cast<const float4*>(out + (size_t)d * DIM + c4);

#pragma unroll
    for (int t = 0; t < N_ETYPES; t++) {
        const int bin = t * N_NODES + d;
        const int n    = __ldg(&g_cnt[bin]);
        if (n == 0) continue;
        const int base = __ldg(&g_off[bin]);
        const __half* WxT = g_Wx + (size_t)t * N_NODES * DIM;

        float4 a0 = make_float4(0.f, 0.f, 0.f, 0.f);
        float4 a1 = make_float4(0.f, 0.f, 0.f, 0.f);
        int j = 0;
        for (; j + 2 <= n; j += 2) {
            int s0 = __ldg(&g_csr[base + j]);
            int s1 = __ldg(&g_csr[base + j + 1]);
            uint2 r0 = *reinterpret_cast<const uint2*>(
                WxT + (size_t)s0 * DIM + c4);
            uint2 r1 = *reinterpret_cast<const uint2*>(
                WxT + (size_t)s1 * DIM + c4);
            float2 p00 = __half22float2(*reinterpret_cast<__half2*>(&r0.x));
            float2 p01 = __half22float2(*reinterpret_cast<__half2*>(&r0.y));
            float2 p10 = __half22float2(*reinterpret_cast<__half2*>(&r1.x));
            float2 p11 = __half22float2(*reinterpret_cast<__half2*>(&r1.y));
            a0.x += p00.x; a0.y += p00.y; a0.z += p01.x; a0.w += p01.y;
            a1.x += p10.x; a1.y += p10.y; a1.z += p11.x; a1.w += p11.y;
        }
        if (j < n) {
            int s0 = __ldg(&g_csr[base + j]);
            uint2 r0 = *reinterpret_cast<const uint2*>(
                WxT + (size_t)s0 * DIM + c4);
            float2 p00 = __half22float2(*reinterpret_cast<__half2*>(&r0.x));
            float2 p01 = __half22float2(*reinterpret_cast<__half2*>(&r0.y));
            a0.x += p00.x; a0.y += p00.y; a0.z += p01.x; a0.w += p01.y;
        }
        float sc = 1.0f / (float)n;
        o.x += (a0.x + a1.x) * sc;
        o.y += (a0.y + a1.y) * sc;
        o.z += (a0.z + a1.z) * sc;
        o.w += (a0.w + a1.w) * sc;
    }

    *reinterpret_cast<float4*>(out + (size_t)d * DIM + c4) = o;
}

// ---------------- launcher ----------------
extern "C" void kernel_launch(void* const* d_in, const int* in_sizes, int n_in,
                              void* d_out, int out_size) {
    const float* x      = (const float*)d_in[0];   // [200000,128]
    const float* W      = (const float*)d_in[1];   // [4,128,128]
    const float* b      = (const float*)d_in[2];   // [4,128]
    const float* W_self = (const float*)d_in[3];   // [128,128]
    const float* b_self = (const float*)d_in[4];   // [128]
    const int*   src    = (const int*)d_in[5];     // [4,500000]
    const int*   dst    = (const int*)d_in[6];     // [4,500000]
    float* out = (float*)d_out;                    // [200000,128]

    (void)in_sizes; (void)n_in; (void)out_size;

    // --- CSR build: count -> scan -> bucket ---
    zero_cnt_kernel<<<(M_BINS + 255) / 256, 256>>>();
    count_kernel<<<(TOTAL_EDGES + 255) / 256, 256>>>(dst);
    scan_sums_kernel<<<NB, SCAN_B>>>();
    scan_tops_kernel<<<1, SCAN_B>>>();
    scan_final_kernel<<<NB, SCAN_B>>>();
    bucket_kernel<<<(TOTAL_EDGES + 255) / 256, 256>>>(src, dst);

    // --- fused 5-way tf32 GEMM: Wx[0..3] fp16 scratch + self message into out
    cudaFuncSetAttribute(gemm_fused_kernel,
                         cudaFuncAttributeMaxDynamicSharedMemorySize,
                         SMEM_BYTES);
    int grid = (N_NODES + BM - 1) / BM;
    gemm_fused_kernel<<<grid, 256, SMEM_BYTES>>>(x, W, b, W_self, b_self, out);

    // --- CSR gather-sum: out[d] += sum_t mean_{src in N_t(d)} Wx[t][src] ---
    {
        long long threads = (long long)N_NODES * 32;
        int blocks = (int)((threads + 255) / 256);
        gather_sum_kernel<<<blocks, 256>>>(out);
    }
}

// round 17
// speedup vs baseline: 1.1802x; 1.0079x over previous
#include <cuda_runtime.h>
#include <cuda_fp16.h>
#include <stdint.h>

#define N_NODES 200000
#define N_ETYPES 4
#define N_EDGES 500000
#define DIM 128
#define M_BINS (N_ETYPES * N_NODES)       // 800000 (etype, dst) bins
#define TOTAL_EDGES (N_ETYPES * N_EDGES)  // 2000000
#define SCAN_B 1024
#define NB ((M_BINS + SCAN_B - 1) / SCAN_B)   // 782 scan blocks

// ---------------- scratch (static __device__ — no allocations) ----------------
__device__ __half g_Wx[(size_t)N_ETYPES * N_NODES * DIM];  // 204.8 MB (fp16)
__device__ int g_cnt[M_BINS];        // per-(etype,dst) in-degree
__device__ int g_off[M_BINS];        // CSR row offsets (exclusive scan of cnt)
__device__ int g_cur[M_BINS];        // bucket cursors (copy of offsets)
__device__ int g_csr[TOTAL_EDGES];   // src node ids grouped by (etype,dst)
__device__ int g_bsum[SCAN_B];       // scan block sums (NB <= 1024)

// ---------------- prep kernels -------------------------------------------------
__global__ void zero_cnt_kernel() {
    int i = blockIdx.x * blockDim.x + threadIdx.x;
    if (i < M_BINS) g_cnt[i] = 0;
}

__global__ void count_kernel(const int* __restrict__ dst) {
    int i = blockIdx.x * blockDim.x + threadIdx.x;
    if (i < TOTAL_EDGES) {
        int t = i / N_EDGES;
        atomicAdd(&g_cnt[t * N_NODES + dst[i]], 1);
    }
}

__global__ __launch_bounds__(SCAN_B)
void scan_sums_kernel() {
    __shared__ int s[SCAN_B];
    int t = threadIdx.x;
    int i = blockIdx.x * SCAN_B + t;
    s[t] = (i < M_BINS) ? g_cnt[i] : 0;
    __syncthreads();
#pragma unroll
    for (int o = SCAN_B / 2; o > 0; o >>= 1) {
        if (t < o) s[t] += s[t + o];
        __syncthreads();
    }
    if (t == 0) g_bsum[blockIdx.x] = s[0];
}

__global__ __launch_bounds__(SCAN_B)
void scan_tops_kernel() {
    __shared__ int s[SCAN_B];
    int t = threadIdx.x;
    int own = (t < NB) ? g_bsum[t] : 0;
    s[t] = own;
    __syncthreads();
#pragma unroll
    for (int o = 1; o < SCAN_B; o <<= 1) {
        int v = (t >= o) ? s[t - o] : 0;
        __syncthreads();
        s[t] += v;
        __syncthreads();
    }
    if (t < NB) g_bsum[t] = s[t] - own;   // exclusive
}

__global__ __launch_bounds__(SCAN_B)
void scan_final_kernel() {
    __shared__ int s[SCAN_B];
    int t = threadIdx.x;
    int i = blockIdx.x * SCAN_B + t;
    int own = (i < M_BINS) ? g_cnt[i] : 0;
    s[t] = own;
    __syncthreads();
#pragma unroll
    for (int o = 1; o < SCAN_B; o <<= 1) {
        int v = (t >= o) ? s[t - o] : 0;
        __syncthreads();
        s[t] += v;
        __syncthreads();
    }
    if (i < M_BINS) {
        int ex = s[t] - own + g_bsum[blockIdx.x];
        g_off[i] = ex;
        g_cur[i] = ex;
    }
}

__global__ void bucket_kernel(const int* __restrict__ src,
                              const int* __restrict__ dst) {
    int i = blockIdx.x * blockDim.x + threadIdx.x;
    if (i < TOTAL_EDGES) {
        int t = i / N_EDGES;
        int pos = atomicAdd(&g_cur[t * N_NODES + dst[i]], 1);
        g_csr[pos] = src[i];
    }
}

// ---------------- kernel: fused 5-way TF32 GEMM (R15-proven, unchanged) -------
// One block owns a 128-row tile of x (tf32 in smem, loaded ONCE), loops bt=0..4
// over the 5 weight matrices with cp.async double-buffered B tiles.
// bt<4 -> g_Wx[bt] scratch in FP16, bt==4 -> fp32 self message into out.
// 256 threads = 8 warps in 2(m) x 4(n); warp tile 64x32 = 4 m16 x 4 n8.

#define BM 128
#define AS 132    // A smem stride: frag bank = (4g+tg)%32 -> conflict-free
#define BSD 136   // B smem stride: frag bank = (8tg+g)%32 -> conflict-free
#define SMEM_FLOATS (BM * AS + 2 * DIM * BSD)
#define SMEM_BYTES (SMEM_FLOATS * 4)

__device__ __forceinline__ uint32_t f2tf32(float f) {
    uint32_t u;
    asm("cvt.rna.tf32.f32 %0, %1;" : "=r"(u) : "f"(f));
    return u;
}

__device__ __forceinline__ void mma_tf32(float c[4], const uint32_t a[4],
                                         const uint32_t bb[2]) {
    asm volatile(
        "mma.sync.aligned.m16n8k8.row.col.f32.tf32.tf32.f32 "
        "{%0,%1,%2,%3}, {%4,%5,%6,%7}, {%8,%9}, {%0,%1,%2,%3};"
        : "+f"(c[0]), "+f"(c[1]), "+f"(c[2]), "+f"(c[3])
        : "r"(a[0]), "r"(a[1]), "r"(a[2]), "r"(a[3]), "r"(bb[0]), "r"(bb[1]));
}

__device__ __forceinline__ void cp_async_tile(float* sdst,
                                              const float* __restrict__ gsrc,
                                              int tid) {
#pragma unroll
    for (int it = 0; it < 16; it++) {
        int idx = tid + it * 256;
        int r   = idx >> 5;            // 0..127
        int c4  = (idx & 31) * 4;      // 0..124
        uint32_t s = (uint32_t)__cvta_generic_to_shared(sdst + r * BSD + c4);
        asm volatile("cp.async.ca.shared.global [%0], [%1], 16;"
                     :: "r"(s), "l"(gsrc + (size_t)r * DIM + c4));
    }
}

__global__ __launch_bounds__(256)
void gemm_fused_kernel(const float* __restrict__ x,
                       const float* __restrict__ W,
                       const float* __restrict__ b,
                       const float* __restrict__ W_self,
                       const float* __restrict__ b_self,
                       float* __restrict__ out) {
    extern __shared__ float smem[];
    float* As    = smem;                 // [BM][AS], tf32 bit patterns
    float* BsAll = smem + BM * AS;       // [2][DIM][BSD], raw fp32 via cp.async

    const int row0 = blockIdx.x * BM;
    const int tid  = threadIdx.x;
    const int warp = tid >> 5;
    const int lane = tid & 31;
    const int wm   = warp >> 2;        // 0..1
    const int wn   = warp & 3;         // 0..3
    const int g    = lane >> 2;        // 0..7
    const int tg   = lane & 3;         // 0..3

    const float* Bm[5] = {W, W + DIM * DIM, W + 2 * DIM * DIM,
                          W + 3 * DIM * DIM, W_self};
    const float* bi[5] = {b, b + DIM, b + 2 * DIM, b + 3 * DIM, b_self};

    cp_async_tile(BsAll, Bm[0], tid);
    asm volatile("cp.async.commit_group;");

    // stage A tile once: 128x128 fp32 -> tf32 in smem
#pragma unroll
    for (int it = 0; it < 16; it++) {
        int idx = tid + it * 256;
        int r   = idx >> 5;
        int c4  = (idx & 31) * 4;
        int gr  = row0 + r;
        float4 v = make_float4(0.f, 0.f, 0.f, 0.f);
        if (gr < N_NODES)
            v = *reinterpret_cast<const float4*>(x + (size_t)gr * DIM + c4);
        uint4 t;
        t.x = f2tf32(v.x); t.y = f2tf32(v.y);
        t.z = f2tf32(v.z); t.w = f2tf32(v.w);
        *reinterpret_cast<uint4*>(&As[r * AS + c4]) = t;
    }

    float acc[4][4][4];

    for (int bt = 0; bt < 5; bt++) {
        float* Bbuf = BsAll + (bt & 1) * (DIM * BSD);

        asm volatile("cp.async.wait_group 0;" ::: "memory");
        __syncthreads();

        if (bt < 4) {
            cp_async_tile(BsAll + ((bt + 1) & 1) * (DIM * BSD), Bm[bt + 1], tid);
            asm volatile("cp.async.commit_group;");
        }

#pragma unroll
        for (int i = 0; i < 4; i++)
#pragma unroll
            for (int j = 0; j < 4; j++)
#pragma unroll
                for (int k = 0; k < 4; k++) acc[i][j][k] = 0.0f;

#pragma unroll
        for (int ks = 0; ks < DIM; ks += 8) {
            uint32_t afr[4][4];
#pragma unroll
            for (int mt = 0; mt < 4; mt++) {
                int r = wm * 64 + mt * 16 + g;
                afr[mt][0] = __float_as_uint(As[r * AS + ks + tg]);
                afr[mt][1] = __float_as_uint(As[(r + 8) * AS + ks + tg]);
                afr[mt][2] = __float_as_uint(As[r * AS + ks + tg + 4]);
                afr[mt][3] = __float_as_uint(As[(r + 8) * AS + ks + tg + 4]);
            }
            uint32_t bfr[4][2];
#pragma unroll
            for (int nt = 0; nt < 4; nt++) {
                int c = wn * 32 + nt * 8 + g;
                bfr[nt][0] = f2tf32(Bbuf[(ks + tg) * BSD + c]);
                bfr[nt][1] = f2tf32(Bbuf[(ks + tg + 4) * BSD + c]);
            }
#pragma unroll
            for (int mt = 0; mt < 4; mt++)
#pragma unroll
                for (int nt = 0; nt < 4; nt++)
                    mma_tf32(acc[mt][nt], afr[mt], bfr[nt]);
        }

        const float* bias = bi[bt];
        if (bt < 4) {
            __half* C = g_Wx + ((size_t)bt * N_NODES + row0) * DIM;
#pragma unroll
            for (int nt = 0; nt < 4; nt++) {
                int c = wn * 32 + nt * 8 + tg * 2;
                float b0 = __ldg(&bias[c]);
                float b1 = __ldg(&bias[c + 1]);
#pragma unroll
                for (int mt = 0; mt < 4; mt++) {
                    int r_lo = wm * 64 + mt * 16 + g;
                    if (row0 + r_lo < N_NODES) {
                        __half2 h = __floats2half2_rn(acc[mt][nt][0] + b0,
                                                      acc[mt][nt][1] + b1);
                        *reinterpret_cast<__half2*>(
                            C + (size_t)r_lo * DIM + c) = h;
                    }
                    if (row0 + r_lo + 8 < N_NODES) {
                        __half2 h = __floats2half2_rn(acc[mt][nt][2] + b0,
                                                      acc[mt][nt][3] + b1);
                        *reinterpret_cast<__half2*>(
                            C + (size_t)(r_lo + 8) * DIM + c) = h;
                    }
                }
            }
        } else {
            float* C = out + (size_t)row0 * DIM;
#pragma unroll
            for (int nt = 0; nt < 4; nt++) {
                int c = wn * 32 + nt * 8 + tg * 2;
                float b0 = __ldg(&bias[c]);
                float b1 = __ldg(&bias[c + 1]);
#pragma unroll
                for (int mt = 0; mt < 4; mt++) {
                    int r_lo = wm * 64 + mt * 16 + g;
                    if (row0 + r_lo < N_NODES) {
                        float2 v0 = make_float2(acc[mt][nt][0] + b0,
                                                acc[mt][nt][1] + b1);
                        *reinterpret_cast<float2*>(
                            C + (size_t)r_lo * DIM + c) = v0;
                    }
                    if (row0 + r_lo + 8 < N_NODES) {
                        float2 v1 = make_float2(acc[mt][nt][2] + b0,
                                                acc[mt][nt][3] + b1);
                        *reinterpret_cast<float2*>(
                            C + (size_t)(r_lo + 8) * DIM + c) = v1;
                    }
                }
            }
        }
    }
}

// ---------------- kernel: CSR gather-sum, 2 dst nodes per warp ----------------
// fp16 rows are 256B, so 16 lanes cover a row at 16B (uint4) per lane. Each
// warp processes two dst nodes concurrently (lanes 0-15 -> 2w, 16-31 -> 2w+1),
// doubling independent load chains per warp. Per half-warp: sequential etypes,
// unroll-2 edge walk, fp32 accumulation, single pair of float4 stores.
__global__ __launch_bounds__(256)
void gather_sum_kernel(float* __restrict__ out) {
    int w    = (blockIdx.x * blockDim.x + threadIdx.x) >> 5;
    int lane = threadIdx.x & 31;
    int half = lane >> 4;               // 0 or 1
    int hl   = lane & 15;               // lane within half-warp
    int d    = w * 2 + half;
    if (d >= N_NODES) return;
    const int e0 = hl * 8;              // element offset (8 fp16 per lane)

    // self message slice (8 floats)
    float4 o0 = *reinterpret_cast<const float4*>(out + (size_t)d * DIM + e0);
    float4 o1 = *reinterpret_cast<const float4*>(out + (size_t)d * DIM + e0 + 4);

#pragma unroll
    for (int t = 0; t < N_ETYPES; t++) {
        const int bin = t * N_NODES + d;
        const int n    = __ldg(&g_cnt[bin]);
        if (n == 0) continue;
        const int base = __ldg(&g_off[bin]);
        const __half* WxT = g_Wx + (size_t)t * N_NODES * DIM;

        float a0[8] = {0.f, 0.f, 0.f, 0.f, 0.f, 0.f, 0.f, 0.f};
        float a1[8] = {0.f, 0.f, 0.f, 0.f, 0.f, 0.f, 0.f, 0.f};
        int j = 0;
        for (; j + 2 <= n; j += 2) {
            int s0 = __ldg(&g_csr[base + j]);
            int s1 = __ldg(&g_csr[base + j + 1]);
            uint4 r0 = *reinterpret_cast<const uint4*>(
                WxT + (size_t)s0 * DIM + e0);
            uint4 r1 = *reinterpret_cast<const uint4*>(
                WxT + (size_t)s1 * DIM + e0);
            const __half2* h0 = reinterpret_cast<const __half2*>(&r0);
            const __half2* h1 = reinterpret_cast<const __half2*>(&r1);
#pragma unroll
            for (int q = 0; q < 4; q++) {
                float2 p0 = __half22float2(h0[q]);
                float2 p1 = __half22float2(h1[q]);
                a0[q * 2]     += p0.x;
                a0[q * 2 + 1] += p0.y;
                a1[q * 2]     += p1.x;
                a1[q * 2 + 1] += p1.y;
            }
        }
        if (j < n) {
            int s0 = __ldg(&g_csr[base + j]);
            uint4 r0 = *reinterpret_cast<const uint4*>(
                WxT + (size_t)s0 * DIM + e0);
            const __half2* h0 = reinterpret_cast<const __half2*>(&r0);
#pragma unroll
            for (int q = 0; q < 4; q++) {
                float2 p0 = __half22float2(h0[q]);
                a0[q * 2]     += p0.x;
                a0[q * 2 + 1] += p0.y;
            }
        }
        float sc = 1.0f / (float)n;
        o0.x += (a0[0] + a1[0]) * sc;
        o0.y += (a0[1] + a1[1]) * sc;
        o0.z += (a0[2] + a1[2]) * sc;
        o0.w += (a0[3] + a1[3]) * sc;
        o1.x += (a0[4] + a1[4]) * sc;
        o1.y += (a0[5] + a1[5]) * sc;
        o1.z += (a0[6] + a1[6]) * sc;
        o1.w += (a0[7] + a1[7]) * sc;
    }

    *reinterpret_cast<float4*>(out + (size_t)d * DIM + e0)     = o0;
    *reinterpret_cast<float4*>(out + (size_t)d * DIM + e0 + 4) = o1;
}

// ---------------- launcher ----------------
extern "C" void kernel_launch(void* const* d_in, const int* in_sizes, int n_in,
                              void* d_out, int out_size) {
    const float* x      = (const float*)d_in[0];   // [200000,128]
    const float* W      = (const float*)d_in[1];   // [4,128,128]
    const float* b      = (const float*)d_in[2];   // [4,128]
    const float* W_self = (const float*)d_in[3];   // [128,128]
    const float* b_self = (const float*)d_in[4];   // [128]
    const int*   src    = (const int*)d_in[5];     // [4,500000]
    const int*   dst    = (const int*)d_in[6];     // [4,500000]
    float* out = (float*)d_out;                    // [200000,128]

    (void)in_sizes; (void)n_in; (void)out_size;

    // --- CSR build: count -> scan -> bucket ---
    zero_cnt_kernel<<<(M_BINS + 255) / 256, 256>>>();
    count_kernel<<<(TOTAL_EDGES + 255) / 256, 256>>>(dst);
    scan_sums_kernel<<<NB, SCAN_B>>>();
    scan_tops_kernel<<<1, SCAN_B>>>();
    scan_final_kernel<<<NB, SCAN_B>>>();
    bucket_kernel<<<(TOTAL_EDGES + 255) / 256, 256>>>(src, dst);

    // --- fused 5-way tf32 GEMM: Wx[0..3] fp16 scratch + self message into out
    cudaFuncSetAttribute(gemm_fused_kernel,
                         cudaFuncAttributeMaxDynamicSharedMemorySize,
                         SMEM_BYTES);
    int grid = (N_NODES + BM - 1) / BM;
    gemm_fused_kernel<<<grid, 256, SMEM_BYTES>>>(x, W, b, W_self, b_self, out);

    // --- CSR gather-sum: out[d] += sum_t mean_{src in N_t(d)} Wx[t][src] ---
    {
        long long warps = (N_NODES + 1) / 2;
        long long threads = warps * 32;
        int blocks = (int)((threads + 255) / 256);
        gather_sum_kernel<<<blocks, 256>>>(out);
    }
}